// round 15
// baseline (speedup 1.0000x reference)
#include <cuda_runtime.h>
#include <cuda_bf16.h>
#include <cstdint>

#define NN 4096
#define DD 512
#define NTILE 32        // NN / 128
#define NBLK  528       // NTILE*(NTILE+1)/2
#define BK    64        // k-slab width in bf16
#define STR   72        // smem row stride in bf16 (64 + 8 pad) -> 144 B
#define STAGE_B (128 * STR * 2)          // bytes per tile stage (18432)
#define SMEM_DYN (4 * STAGE_B)           // A,B x 2 stages = 73728 B

static __device__ __nv_bfloat16 g_w[NN * DD];   // normalized * sqrt(10), bf16
static __device__ float g_S[NN];                // sum_j!=i exp(sim_ij)
static __device__ float g_P[NN];                // sum_{same label, j!=i} sim_ij
static __device__ int   g_lab[NN];
static __device__ unsigned g_ctr;               // CTA retirement counter

// ---------------------------------------------------------------------------
__device__ __forceinline__ void cp_async16(uint32_t dst, const void* src) {
    asm volatile("cp.async.cg.shared.global [%0], [%1], 16;"
                 :: "r"(dst), "l"(src) : "memory");
}
__device__ __forceinline__ void ldsm4(uint32_t* r, uint32_t addr) {
    asm volatile("ldmatrix.sync.aligned.m8n8.x4.shared.b16 {%0,%1,%2,%3}, [%4];"
                 : "=r"(r[0]), "=r"(r[1]), "=r"(r[2]), "=r"(r[3]) : "r"(addr));
}

// ---------------------------------------------------------------------------
// Warp-per-row prep: zero S/P + label extraction (dtype-agnostic) + normalize.
// Labels buffer viewed as int32 (in-bounds for int32 or int64 layout). If true
// dtype is int64 (LE, values < 2^31), all odd 32-bit words are 0; with int32
// labels in [0,100) that's ~impossible over 32 samples.
__global__ __launch_bounds__(256) void norm_kernel(const float* __restrict__ x,
                                                   const int* __restrict__ lab32) {
    __shared__ int nz;
    const int tid = threadIdx.x;
    const int warp = tid >> 5, lane = tid & 31;
    const int row = blockIdx.x * 8 + warp;

    if (tid == 0) { nz = 0; if (blockIdx.x == 0) g_ctr = 0; }
    __syncthreads();
    if (tid < 64 && (tid & 1) && lab32[tid] != 0) atomicAdd(&nz, 1);

    const float4* xr = (const float4*)(x + (size_t)row * DD + lane * 16);
    float4 v[4];
    float s = 0.f;
#pragma unroll
    for (int k = 0; k < 4; k++) {
        v[k] = xr[k];
        s += v[k].x * v[k].x + v[k].y * v[k].y + v[k].z * v[k].z + v[k].w * v[k].w;
    }
#pragma unroll
    for (int m = 16; m; m >>= 1) s += __shfl_xor_sync(0xffffffffu, s, m);
    const float scale = sqrtf(10.f) * rsqrtf(s);

    uint32_t o[8];
#pragma unroll
    for (int k = 0; k < 4; k++) {
        __nv_bfloat162 p0 = __floats2bfloat162_rn(v[k].x * scale, v[k].y * scale);
        __nv_bfloat162 p1 = __floats2bfloat162_rn(v[k].z * scale, v[k].w * scale);
        o[2 * k]     = *(uint32_t*)&p0;
        o[2 * k + 1] = *(uint32_t*)&p1;
    }
    uint4* dst = (uint4*)(g_w + (size_t)row * DD + lane * 16);
    dst[0] = make_uint4(o[0], o[1], o[2], o[3]);
    dst[1] = make_uint4(o[4], o[5], o[6], o[7]);

    __syncthreads();
    if (lane == 0) {
        bool is64 = (nz == 0);
        g_lab[row] = is64 ? lab32[2 * row] : lab32[row];
        g_S[row] = 0.f;
        g_P[row] = 0.f;
    }
}

// ---------------------------------------------------------------------------
// Fused symmetric GEMM + SupCon epilogue + last-CTA finalization.
// 128x128 tile, upper-tri pairs, 256 threads (warp grid 4Mx2N, warp 32x64).
// BK=64 cp.async double buffer + FRAGMENT PING-PONG across kk-steps:
// LDSM for kk+1 issued before HMMA of kk -> smem latency hidden.
__global__ __launch_bounds__(256, 2) void gemm_kernel(float* __restrict__ out) {
    extern __shared__ __align__(16) char dyn[];

    int b = blockIdx.x;
    int bi = 0;
    while (b >= NTILE - bi) { b -= NTILE - bi; bi++; }
    int bj = bi + b;
    const int iBase = bi * 128, jBase = bj * 128;
    const bool diagTile = (bi == bj);

    const int tid = threadIdx.x;
    const int warp = tid >> 5, lane = tid & 31;
    const int wm = warp >> 1, wn = warp & 1;
    const int qr = lane >> 2, qc = lane & 3;

    float acc[2][8][4];
#pragma unroll
    for (int mt = 0; mt < 2; mt++)
#pragma unroll
        for (int nt = 0; nt < 8; nt++)
#pragma unroll
            for (int c = 0; c < 4; c++) acc[mt][nt][c] = 0.f;

    const int aRow  = wm * 32 + (lane & 7) + ((lane >> 3) & 1) * 8;
    const int aColB = ((lane >> 4) & 1) * 16;
    const int bRow  = wn * 64 + (lane & 7) + ((lane >> 4) & 1) * 8;
    const int bColB = ((lane >> 3) & 1) * 16;

    const uint32_t smBase = (uint32_t)__cvta_generic_to_shared(dyn);
    const uint32_t aBase0 = smBase;
    const uint32_t bBase0 = smBase + 2 * STAGE_B;

    const int ldRow = tid >> 3;          // 0..31 (+32 per round)
    const int ldC   = (tid & 7) * 16;    // byte col 0..112

    auto issue = [&](int it) {
        const int k0 = it * BK;
        const uint32_t aDst = aBase0 + (uint32_t)((it & 1) * STAGE_B);
        const uint32_t bDst = bBase0 + (uint32_t)((it & 1) * STAGE_B);
        const __nv_bfloat16* aSrc = g_w + (size_t)(iBase + ldRow) * DD + k0 + (tid & 7) * 8;
        const __nv_bfloat16* bSrc = g_w + (size_t)(jBase + ldRow) * DD + k0 + (tid & 7) * 8;
#pragma unroll
        for (int r = 0; r < 4; r++) {
            int row = ldRow + 32 * r;
            cp_async16(aDst + row * (STR * 2) + ldC, aSrc + (size_t)(32 * r) * DD);
            cp_async16(bDst + row * (STR * 2) + ldC, bSrc + (size_t)(32 * r) * DD);
        }
        asm volatile("cp.async.commit_group;" ::: "memory");
    };

    uint32_t afr[2][2][4], bfr[2][4][4];   // ping-pong fragment buffers

    issue(0);
    for (int it = 0; it < DD / BK; it++) {
        if (it + 1 < DD / BK) {
            issue(it + 1);
            asm volatile("cp.async.wait_group 1;" ::: "memory");
        } else {
            asm volatile("cp.async.wait_group 0;" ::: "memory");
        }
        __syncthreads();

        const uint32_t aB = aBase0 + (uint32_t)((it & 1) * STAGE_B);
        const uint32_t bB = bBase0 + (uint32_t)((it & 1) * STAGE_B);

        // preload kk=0 fragments into buffer 0
#pragma unroll
        for (int mt = 0; mt < 2; mt++)
            ldsm4(afr[0][mt], aB + (uint32_t)((aRow + mt * 16) * (STR * 2) + aColB));
#pragma unroll
        for (int np = 0; np < 4; np++)
            ldsm4(bfr[0][np], bB + (uint32_t)((bRow + np * 16) * (STR * 2) + bColB));

#pragma unroll
        for (int kk16 = 0; kk16 < 4; kk16++) {
            const int cur = kk16 & 1, nxt = cur ^ 1;
            if (kk16 < 3) {   // issue next kk-step's LDSMs before this step's HMMAs
                const int kOff = (kk16 + 1) * 32;   // bytes: 16 bf16
#pragma unroll
                for (int mt = 0; mt < 2; mt++)
                    ldsm4(afr[nxt][mt],
                          aB + (uint32_t)((aRow + mt * 16) * (STR * 2) + kOff + aColB));
#pragma unroll
                for (int np = 0; np < 4; np++)
                    ldsm4(bfr[nxt][np],
                          bB + (uint32_t)((bRow + np * 16) * (STR * 2) + kOff + bColB));
            }
#pragma unroll
            for (int mt = 0; mt < 2; mt++)
#pragma unroll
                for (int nt = 0; nt < 8; nt++) {
                    int np = nt >> 1, hi = nt & 1;
                    uint32_t b0 = bfr[cur][np][hi ? 2 : 0], b1 = bfr[cur][np][hi ? 3 : 1];
                    asm volatile(
                        "mma.sync.aligned.m16n8k16.row.col.f32.bf16.bf16.f32 "
                        "{%0,%1,%2,%3},{%4,%5,%6,%7},{%8,%9},{%0,%1,%2,%3};"
                        : "+f"(acc[mt][nt][0]), "+f"(acc[mt][nt][1]),
                          "+f"(acc[mt][nt][2]), "+f"(acc[mt][nt][3])
                        : "r"(afr[cur][mt][0]), "r"(afr[cur][mt][1]),
                          "r"(afr[cur][mt][2]), "r"(afr[cur][mt][3]),
                          "r"(b0), "r"(b1));
                }
        }
        __syncthreads();
    }

    // ---- fused epilogue (column-outer; low register pressure) ----
    int* labI = (int*)dyn;
    int* labJ = labI + 128;
    if (tid < 128) { labI[tid] = g_lab[iBase + tid]; labJ[tid] = g_lab[jBase + tid]; }
    __syncthreads();

    float rowE[2][2] = {{0.f, 0.f}, {0.f, 0.f}};
    float rowP[2][2] = {{0.f, 0.f}, {0.f, 0.f}};

#pragma unroll
    for (int nt = 0; nt < 8; nt++) {
#pragma unroll
        for (int cc = 0; cc < 2; cc++) {
            const int jLoc = wn * 64 + nt * 8 + qc * 2 + cc;
            const int gj = jBase + jLoc;
            const int lj = labJ[jLoc];
            float cE = 0.f, cP = 0.f;
#pragma unroll
            for (int mt = 0; mt < 2; mt++) {
#pragma unroll
                for (int h = 0; h < 2; h++) {
                    const int iLoc = wm * 32 + mt * 16 + qr + h * 8;
                    const int gi = iBase + iLoc;
                    float s = acc[mt][nt][h * 2 + cc];
                    float e = __expf(s);
                    float p = (labI[iLoc] == lj) ? s : 0.f;
                    bool ok = (gi != gj);
                    e = ok ? e : 0.f;
                    p = ok ? p : 0.f;
                    rowE[mt][h] += e;
                    rowP[mt][h] += p;
                    cE += e;
                    cP += p;
                }
            }
            if (!diagTile) {
                cE += __shfl_xor_sync(0xffffffffu, cE, 4);
                cE += __shfl_xor_sync(0xffffffffu, cE, 8);
                cE += __shfl_xor_sync(0xffffffffu, cE, 16);
                cP += __shfl_xor_sync(0xffffffffu, cP, 4);
                cP += __shfl_xor_sync(0xffffffffu, cP, 8);
                cP += __shfl_xor_sync(0xffffffffu, cP, 16);
                if (qr == 0) {
                    atomicAdd(&g_S[gj], cE);
                    atomicAdd(&g_P[gj], cP);
                }
            }
        }
    }

#pragma unroll
    for (int mt = 0; mt < 2; mt++)
#pragma unroll
        for (int h = 0; h < 2; h++) {
            float rE = rowE[mt][h], rP = rowP[mt][h];
            rE += __shfl_xor_sync(0xffffffffu, rE, 1);
            rE += __shfl_xor_sync(0xffffffffu, rE, 2);
            rP += __shfl_xor_sync(0xffffffffu, rP, 1);
            rP += __shfl_xor_sync(0xffffffffu, rP, 2);
            if (qc == 0) {
                const int gi = iBase + wm * 32 + mt * 16 + qr + h * 8;
                atomicAdd(&g_S[gi], rE);
                atomicAdd(&g_P[gi], rP);
            }
        }

    // ---- last CTA finalizes (threadfence-reduction pattern) ----
    __syncthreads();
    __shared__ unsigned lastFlag;
    if (tid == 0) {
        __threadfence();
        lastFlag = (atomicAdd(&g_ctr, 1u) == (unsigned)(NBLK - 1));
    }
    __syncthreads();
    if (lastFlag) {
        int* cnt = (int*)(dyn + 1024);
        float* red = (float*)(dyn + 2048);
        if (tid < 128) cnt[tid] = 0;
        __syncthreads();
        for (int i = tid; i < NN; i += 256) atomicAdd(&cnt[g_lab[i] & 127], 1);
        __syncthreads();
        float s = 0.f;
        for (int i = tid; i < NN; i += 256) {
            float C = (float)(cnt[g_lab[i] & 127] - 1);
            float Sv = __ldcg(&g_S[i]);
            float Pv = __ldcg(&g_P[i]);
            s += (Pv - C * logf(Sv)) / (C + 1e-8f);
        }
        red[tid] = s;
        __syncthreads();
        for (int st = 128; st; st >>= 1) {
            if (tid < st) red[tid] += red[tid + st];
            __syncthreads();
        }
        if (tid == 0) out[0] = -red[0] / (float)NN;
    }
}

// ---------------------------------------------------------------------------
extern "C" void kernel_launch(void* const* d_in, const int* in_sizes, int n_in,
                              void* d_out, int out_size) {
    const float* features = (const float*)d_in[0];
    const int* labels32 = (const int*)d_in[1];   // int32 view; layout auto-detected
    float* out = (float*)d_out;

    cudaFuncSetAttribute(gemm_kernel,
                         cudaFuncAttributeMaxDynamicSharedMemorySize, SMEM_DYN);

    norm_kernel<<<NN / 8, 256>>>(features, labels32);
    gemm_kernel<<<NBLK, 256, SMEM_DYN>>>(out);
}